// round 1
// baseline (speedup 1.0000x reference)
#include <cuda_runtime.h>

#define B_ 16384
#define D_ 4096
#define E_ 4
#define O_ 256

#define BM 64
#define BN 64
#define BK 32

// Gate weight per (row, expert); 0 for unselected experts. 256 KB scratch.
__device__ float g_gates[B_ * E_];

// ---------------------------------------------------------------------------
// Kernel 1: router logits -> softmax -> top-2 -> gates (+ routing_weights out)
// One warp per row. v row = 16KB streamed via float4; router_w [4096,4] is
// exactly one float4 per d, cached in L1/L2.
// ---------------------------------------------------------------------------
__global__ __launch_bounds__(256) void router_kernel(
    const float* __restrict__ v, const float* __restrict__ rw,
    float* __restrict__ routing_out, int write_routing)
{
    int warp = (blockIdx.x * blockDim.x + threadIdx.x) >> 5;
    int lane = threadIdx.x & 31;
    if (warp >= B_) return;

    const float4* v4  = (const float4*)(v + (size_t)warp * D_);
    const float4* rw4 = (const float4*)rw;  // rw[d] is a float4 over experts

    float4 acc = make_float4(0.f, 0.f, 0.f, 0.f);
    #pragma unroll 4
    for (int i = lane; i < D_ / 4; i += 32) {
        float4 vv = v4[i];
        float4 r0 = rw4[4 * i + 0];
        float4 r1 = rw4[4 * i + 1];
        float4 r2 = rw4[4 * i + 2];
        float4 r3 = rw4[4 * i + 3];
        acc.x += vv.x * r0.x + vv.y * r1.x + vv.z * r2.x + vv.w * r3.x;
        acc.y += vv.x * r0.y + vv.y * r1.y + vv.z * r2.y + vv.w * r3.y;
        acc.z += vv.x * r0.z + vv.y * r1.z + vv.z * r2.z + vv.w * r3.z;
        acc.w += vv.x * r0.w + vv.y * r1.w + vv.z * r2.w + vv.w * r3.w;
    }
    #pragma unroll
    for (int off = 16; off; off >>= 1) {
        acc.x += __shfl_xor_sync(0xFFFFFFFFu, acc.x, off);
        acc.y += __shfl_xor_sync(0xFFFFFFFFu, acc.y, off);
        acc.z += __shfl_xor_sync(0xFFFFFFFFu, acc.z, off);
        acc.w += __shfl_xor_sync(0xFFFFFFFFu, acc.w, off);
    }

    if (lane == 0) {
        float l[E_] = {acc.x, acc.y, acc.z, acc.w};
        float mx = fmaxf(fmaxf(l[0], l[1]), fmaxf(l[2], l[3]));
        float w[E_];
        float s = 0.f;
        #pragma unroll
        for (int e = 0; e < E_; e++) { w[e] = __expf(l[e] - mx); s += w[e]; }
        float inv = 1.f / s;
        #pragma unroll
        for (int e = 0; e < E_; e++) w[e] *= inv;

        if (write_routing) {
            *(float4*)&routing_out[(size_t)warp * E_] =
                make_float4(w[0], w[1], w[2], w[3]);
        }

        // top-2 (strict > keeps lowest index on ties, matching lax.top_k)
        int i1 = 0;
        #pragma unroll
        for (int e = 1; e < E_; e++) if (w[e] > w[i1]) i1 = e;
        int i2 = -1;
        #pragma unroll
        for (int e = 0; e < E_; e++) {
            if (e == i1) continue;
            if (i2 < 0 || w[e] > w[i2]) i2 = e;
        }
        float gs = 1.f / (w[i1] + w[i2]);
        float g[E_] = {0.f, 0.f, 0.f, 0.f};
        g[i1] = w[i1] * gs;
        g[i2] = w[i2] * gs;
        *(float4*)&g_gates[(size_t)warp * E_] = make_float4(g[0], g[1], g[2], g[3]);
    }
}

// ---------------------------------------------------------------------------
// Kernel 2: dense all-expert GEMM with fused gate-combine epilogue.
// Grid: (O/BN, B/BM). Block 256 threads. Per thread: 4x4 micro-tile per
// expert (acc[4][4][4]). Smem: As transposed [BK][BM] + Bs[E][BK][BN] = 40KB.
// ---------------------------------------------------------------------------
__global__ __launch_bounds__(256) void moe_gemm_kernel(
    const float* __restrict__ v, const float* __restrict__ ew,
    float* __restrict__ out)
{
    __shared__ float As[BK][BM];        // As[k][m]
    __shared__ float Bs[E_][BK][BN];    // Bs[e][k][n]

    const int o0 = blockIdx.x * BN;
    const int b0 = blockIdx.y * BM;
    const int tid = threadIdx.x;
    const int tx = tid & 15;
    const int ty = tid >> 4;

    float acc[E_][4][4] = {};

    for (int k0 = 0; k0 < D_; k0 += BK) {
        // --- load A tile (64 x 32 f32), transposed into As[k][m] ---
        {
            int row = tid >> 2;   // 0..63
            int c   = tid & 3;    // 0..3
            const float4* src = (const float4*)(v + (size_t)(b0 + row) * D_ + k0);
            #pragma unroll
            for (int it = 0; it < 2; it++) {
                int c4 = c + it * 4;      // 0..7 -> covers k offsets 4*c4..4*c4+3
                float4 vv = src[c4];
                As[4 * c4 + 0][row] = vv.x;
                As[4 * c4 + 1][row] = vv.y;
                As[4 * c4 + 2][row] = vv.z;
                As[4 * c4 + 3][row] = vv.w;
            }
        }
        // --- load B tiles for all 4 experts (4 x 32 x 64 f32) ---
        {
            #pragma unroll
            for (int it = 0; it < 8; it++) {
                int f   = tid + it * 256;   // float4 index, 0..2047
                int e   = f >> 9;           // /512 (32*16)
                int rem = f & 511;
                int k   = rem >> 4;
                int c4  = rem & 15;
                float4 w4 = ((const float4*)(ew + ((size_t)e * D_ + (k0 + k)) * O_ + o0))[c4];
                *(float4*)&Bs[e][k][c4 * 4] = w4;
            }
        }
        __syncthreads();

        #pragma unroll 8
        for (int kk = 0; kk < BK; kk++) {
            float4 a = *(const float4*)&As[kk][ty * 4];
            float av[4] = {a.x, a.y, a.z, a.w};
            #pragma unroll
            for (int e = 0; e < E_; e++) {
                float4 b = *(const float4*)&Bs[e][kk][tx * 4];
                float bv[4] = {b.x, b.y, b.z, b.w};
                #pragma unroll
                for (int i = 0; i < 4; i++)
                    #pragma unroll
                    for (int j = 0; j < 4; j++)
                        acc[e][i][j] += av[i] * bv[j];
            }
        }
        __syncthreads();
    }

    // --- epilogue: combine with gates, write out ---
    #pragma unroll
    for (int i = 0; i < 4; i++) {
        int row = b0 + ty * 4 + i;
        float4 g = *(const float4*)&g_gates[(size_t)row * E_];
        float gv[4] = {g.x, g.y, g.z, g.w};
        float ov[4];
        #pragma unroll
        for (int j = 0; j < 4; j++) {
            float s = 0.f;
            #pragma unroll
            for (int e = 0; e < E_; e++) s += gv[e] * acc[e][i][j];
            ov[j] = s;
        }
        *(float4*)&out[(size_t)row * O_ + o0 + tx * 4] =
            make_float4(ov[0], ov[1], ov[2], ov[3]);
    }
}

extern "C" void kernel_launch(void* const* d_in, const int* in_sizes, int n_in,
                              void* d_out, int out_size) {
    const float* v  = (const float*)d_in[0];   // v_standard [16384, 4096]
    const float* rw = (const float*)d_in[1];   // router_w   [4096, 4]
    const float* ew = (const float*)d_in[2];   // expert_w   [4, 4096, 256]
    float* out = (float*)d_out;

    // Output layout assumption: flattened tuple = moe_output [B*O] ++ routing [B*E]
    int write_routing = (out_size >= B_ * O_ + B_ * E_) ? 1 : 0;
    float* routing = write_routing ? (out + (size_t)B_ * O_) : nullptr;

    // Router: one warp per row, 8 warps per block
    router_kernel<<<B_ / 8, 256>>>(v, rw, routing, write_routing);

    // Fused all-expert GEMM + gate combine
    dim3 grid(O_ / BN, B_ / BM);
    moe_gemm_kernel<<<grid, 256>>>(v, ew, out);
}

// round 3
// speedup vs baseline: 3.0839x; 3.0839x over previous
#include <cuda_runtime.h>
#include <cstdint>
#include <cstddef>

#define B_ 16384
#define D_ 4096
#define E_ 4
#define O_ 256
#define N_ 1024          // E*O, interleaved as n = o*4 + e

#define BM 128
#define BN 128
#define BK 32
#define SA 36            // padded row stride (floats): (4r+c)%32 distinct -> conflict-free frags
#define NITER (D_/BK)    // 128
#define STAGE_FLOATS (128 * SA)   // 4608 floats = 18KB per tensor per stage

// scratch
__device__ float g_gates[B_ * E_];        // 256 KB: gate per (row, expert), 0 if unselected
__device__ float g_vt[(size_t)B_ * D_];   // 256 MB: tf32-rounded v
__device__ float g_wt[(size_t)N_ * D_];   // 16 MB : tf32-rounded W^T, n = o*4+e interleave

// ---------------- helpers ----------------
__device__ __forceinline__ uint32_t smem_u32(const void* p) {
    uint32_t a;
    asm("{ .reg .u64 t; cvta.to.shared.u64 t, %1; cvt.u32.u64 %0, t; }" : "=r"(a) : "l"(p));
    return a;
}
__device__ __forceinline__ float rna_tf32(float x) {
    float r; asm("cvt.rna.tf32.f32 %0, %1;" : "=f"(r) : "f"(x)); return r;
}
__device__ __forceinline__ void cp16(uint32_t s, const void* g) {
    asm volatile("cp.async.cg.shared.global [%0], [%1], 16;" :: "r"(s), "l"(g));
}
#define CP_COMMIT() asm volatile("cp.async.commit_group;" ::: "memory")
#define CP_WAIT(n)  asm volatile("cp.async.wait_group %0;" :: "n"(n) : "memory")

__device__ __forceinline__ void mma_tf32(float* d, const uint32_t* a, const uint32_t* b) {
    asm volatile(
        "mma.sync.aligned.m16n8k8.row.col.f32.tf32.tf32.f32 "
        "{%0,%1,%2,%3}, {%4,%5,%6,%7}, {%8,%9}, {%0,%1,%2,%3};"
        : "+f"(d[0]), "+f"(d[1]), "+f"(d[2]), "+f"(d[3])
        : "r"(a[0]), "r"(a[1]), "r"(a[2]), "r"(a[3]), "r"(b[0]), "r"(b[1]));
}

// ---------------------------------------------------------------------------
// Kernel 0: transpose + tf32-round expert_w [E,D,O] -> g_wt[(o*4+e)][d]
// ---------------------------------------------------------------------------
__global__ __launch_bounds__(1024) void transpose_w_kernel(const float* __restrict__ ew) {
    __shared__ float t[32][33];
    int e = blockIdx.z, o0 = blockIdx.y * 32, d0 = blockIdx.x * 32;
    int tx = threadIdx.x, ty = threadIdx.y;
    t[ty][tx] = rna_tf32(ew[((size_t)e * D_ + (d0 + ty)) * O_ + (o0 + tx)]);
    __syncthreads();
    g_wt[((size_t)(o0 + ty) * 4 + e) * D_ + (d0 + tx)] = t[tx][ty];
}

// ---------------------------------------------------------------------------
// Kernel 1: router (softmax + top-2 gates) + fused tf32-round of v -> g_vt
// ---------------------------------------------------------------------------
__global__ __launch_bounds__(256) void router_kernel(
    const float* __restrict__ v, const float* __restrict__ rw,
    float* __restrict__ routing_out, int write_routing)
{
    int warp = (blockIdx.x * blockDim.x + threadIdx.x) >> 5;
    int lane = threadIdx.x & 31;
    if (warp >= B_) return;

    const float4* v4  = (const float4*)(v + (size_t)warp * D_);
    float4*       vt4 = (float4*)(g_vt + (size_t)warp * D_);
    const float4* rw4 = (const float4*)rw;

    float4 acc = make_float4(0.f, 0.f, 0.f, 0.f);
    #pragma unroll 4
    for (int i = lane; i < D_ / 4; i += 32) {
        float4 vv = v4[i];
        float4 r0 = rw4[4 * i + 0];
        float4 r1 = rw4[4 * i + 1];
        float4 r2 = rw4[4 * i + 2];
        float4 r3 = rw4[4 * i + 3];
        acc.x += vv.x * r0.x + vv.y * r1.x + vv.z * r2.x + vv.w * r3.x;
        acc.y += vv.x * r0.y + vv.y * r1.y + vv.z * r2.y + vv.w * r3.y;
        acc.z += vv.x * r0.z + vv.y * r1.z + vv.z * r2.z + vv.w * r3.z;
        acc.w += vv.x * r0.w + vv.y * r1.w + vv.z * r2.w + vv.w * r3.w;
        vt4[i] = make_float4(rna_tf32(vv.x), rna_tf32(vv.y), rna_tf32(vv.z), rna_tf32(vv.w));
    }
    #pragma unroll
    for (int off = 16; off; off >>= 1) {
        acc.x += __shfl_xor_sync(0xFFFFFFFFu, acc.x, off);
        acc.y += __shfl_xor_sync(0xFFFFFFFFu, acc.y, off);
        acc.z += __shfl_xor_sync(0xFFFFFFFFu, acc.z, off);
        acc.w += __shfl_xor_sync(0xFFFFFFFFu, acc.w, off);
    }
    if (lane == 0) {
        float l[E_] = {acc.x, acc.y, acc.z, acc.w};
        float mx = fmaxf(fmaxf(l[0], l[1]), fmaxf(l[2], l[3]));
        float w[E_]; float s = 0.f;
        #pragma unroll
        for (int e = 0; e < E_; e++) { w[e] = __expf(l[e] - mx); s += w[e]; }
        float inv = 1.f / s;
        #pragma unroll
        for (int e = 0; e < E_; e++) w[e] *= inv;
        if (write_routing)
            *(float4*)&routing_out[(size_t)warp * E_] = make_float4(w[0], w[1], w[2], w[3]);
        int i1 = 0;
        #pragma unroll
        for (int e = 1; e < E_; e++) if (w[e] > w[i1]) i1 = e;
        int i2 = -1;
        #pragma unroll
        for (int e = 0; e < E_; e++) {
            if (e == i1) continue;
            if (i2 < 0 || w[e] > w[i2]) i2 = e;
        }
        float gs = 1.f / (w[i1] + w[i2]);
        float g[E_] = {0.f, 0.f, 0.f, 0.f};
        g[i1] = w[i1] * gs;
        g[i2] = w[i2] * gs;
        *(float4*)&g_gates[(size_t)warp * E_] = make_float4(g[0], g[1], g[2], g[3]);
    }
}

// ---------------------------------------------------------------------------
// Kernel 2: tf32 mma.sync GEMM, CTA tile 128x128, fused gate-combine epilogue.
// 8 warps as 2(m) x 4(n); warp tile 64x32; 4x4 m16n8k8 micro-tiles.
// Double-buffered cp.async, 72KB dynamic smem, 2 CTAs/SM.
// ---------------------------------------------------------------------------
__device__ __forceinline__ void load_tiles(uint32_t abase, uint32_t bbase, int tid,
                                           int k0,
                                           const float* __restrict__ Asrc,
                                           const float* __restrict__ Bsrc)
{
    #pragma unroll
    for (int i = 0; i < 4; i++) {
        int idx = tid + i * 256;        // 0..1023
        int r  = idx >> 3;              // row 0..127
        int kc = idx & 7;               // 16B chunk 0..7
        uint32_t dst = (uint32_t)(r * SA + kc * 4) * 4u;
        cp16(abase + dst, Asrc + (size_t)r * D_ + k0 + kc * 4);
        cp16(bbase + dst, Bsrc + (size_t)r * D_ + k0 + kc * 4);
    }
    CP_COMMIT();
}

__global__ __launch_bounds__(256, 2) void moe_mma_kernel(float* __restrict__ out)
{
    extern __shared__ float sm[];
    // layout: A0, B0, A1, B1
    uint32_t sb = smem_u32(sm);
    const uint32_t aOff[2] = {0u, 2u * STAGE_FLOATS * 4u};
    const uint32_t bOff[2] = {1u * STAGE_FLOATS * 4u, 3u * STAGE_FLOATS * 4u};

    const int tid = threadIdx.x;
    const int wid = tid >> 5, lane = tid & 31;
    const int warp_m = wid >> 2;        // 0..1  (64 rows each)
    const int warp_n = wid & 3;         // 0..3  (32 cols each)
    const int qid = lane >> 2;          // 0..7
    const int tig = lane & 3;           // 0..3

    const int m0 = blockIdx.y * BM;
    const int n0 = blockIdx.x * BN;

    const float* Asrc = g_vt + (size_t)m0 * D_;
    const float* Bsrc = g_wt + (size_t)n0 * D_;

    float acc[4][4][4] = {};

    load_tiles(sb + aOff[0], sb + bOff[0], tid, 0,     Asrc, Bsrc);
    load_tiles(sb + aOff[1], sb + bOff[1], tid, BK,    Asrc, Bsrc);

    for (int c = 0; c < NITER; c++) {
        int s = c & 1;
        if (c + 2 < NITER) { CP_WAIT(1); } else { CP_WAIT(0); }
        __syncthreads();

        const uint32_t* A = (const uint32_t*)(sm) + (s ? 2 : 0) * STAGE_FLOATS;
        const uint32_t* Bv = (const uint32_t*)(sm) + (s ? 3 : 1) * STAGE_FLOATS;

        #pragma unroll
        for (int kk = 0; kk < 4; kk++) {
            uint32_t af[4][4], bf[4][2];
            int col = kk * 8 + tig;
            #pragma unroll
            for (int i = 0; i < 4; i++) {
                int r = warp_m * 64 + i * 16 + qid;
                af[i][0] = A[r * SA + col];
                af[i][1] = A[(r + 8) * SA + col];
                af[i][2] = A[r * SA + col + 4];
                af[i][3] = A[(r + 8) * SA + col + 4];
            }
            #pragma unroll
            for (int j = 0; j < 4; j++) {
                int n = warp_n * 32 + j * 8 + qid;
                bf[j][0] = Bv[n * SA + col];
                bf[j][1] = Bv[n * SA + col + 4];
            }
            #pragma unroll
            for (int i = 0; i < 4; i++)
                #pragma unroll
                for (int j = 0; j < 4; j++)
                    mma_tf32(acc[i][j], af[i], bf[j]);
        }
        __syncthreads();

        if (c + 2 < NITER)
            load_tiles(sb + aOff[s], sb + bOff[s], tid, (c + 2) * BK, Asrc, Bsrc);
    }

    // ---- epilogue: gate-combine over expert-interleaved n (n = o*4 + e) ----
    // thread's col pair within an 8-wide ntile: cols tig*2, tig*2+1
    // tig 0 -> experts {0,1} of o_even ; tig 1 -> {2,3} of o_even
    // tig 2 -> experts {0,1} of o_odd  ; tig 3 -> {2,3} of o_odd
    const int e0 = (tig & 1) * 2;
    #pragma unroll
    for (int i = 0; i < 4; i++) {
        int r0 = m0 + warp_m * 64 + i * 16 + qid;
        float2 gA = *(const float2*)&g_gates[(size_t)r0 * E_ + e0];
        float2 gB = *(const float2*)&g_gates[(size_t)(r0 + 8) * E_ + e0];
        #pragma unroll
        for (int j = 0; j < 4; j++) {
            int n = n0 + warp_n * 32 + j * 8 + tig * 2;
            int o = n >> 2;
            float pA = gA.x * acc[i][j][0] + gA.y * acc[i][j][1];
            float pB = gB.x * acc[i][j][2] + gB.y * acc[i][j][3];
            pA += __shfl_xor_sync(0xFFFFFFFFu, pA, 1);
            pB += __shfl_xor_sync(0xFFFFFFFFu, pB, 1);
            if ((lane & 1) == 0) {
                out[(size_t)r0 * O_ + o] = pA;
                out[(size_t)(r0 + 8) * O_ + o] = pB;
            }
        }
    }
}

// ---------------------------------------------------------------------------
extern "C" void kernel_launch(void* const* d_in, const int* in_sizes, int n_in,
                              void* d_out, int out_size) {
    const float* v  = (const float*)d_in[0];   // [16384, 4096]
    const float* rw = (const float*)d_in[1];   // [4096, 4]
    const float* ew = (const float*)d_in[2];   // [4, 4096, 256]
    float* out = (float*)d_out;

    int write_routing = (out_size >= B_ * O_ + B_ * E_) ? 1 : 0;
    float* routing = write_routing ? (out + (size_t)B_ * O_) : nullptr;

    transpose_w_kernel<<<dim3(D_ / 32, O_ / 32, E_), dim3(32, 32)>>>(ew);
    router_kernel<<<B_ / 8, 256>>>(v, rw, routing, write_routing);

    const int smem_bytes = 4 * STAGE_FLOATS * sizeof(float);  // 72 KB
    cudaFuncSetAttribute(moe_mma_kernel, cudaFuncAttributeMaxDynamicSharedMemorySize, smem_bytes);
    moe_mma_kernel<<<dim3(N_ / BN, B_ / BM), 256, smem_bytes>>>(out);
}

// round 4
// speedup vs baseline: 4.4717x; 1.4500x over previous
#include <cuda_runtime.h>
#include <cstdint>
#include <cstddef>

#define B_ 16384
#define D_ 4096
#define E_ 4
#define O_ 256
#define NP 512           // pair-bucket GEMM width: 2 experts * 256, n = o*2 + which

#define BM 128
#define BN 128
#define BK 32
#define SA 36            // padded smem row stride (floats) -> conflict-free frags
#define NITER (D_/BK)    // 128
#define STAGE_FLOATS (128 * SA)
#define MAXMB (B_/BM + 5)   // 133: worst-case total m-blocks over 6 buckets

// scratch
__device__ int    g_cnt[8];                   // bucket counts (reset each launch)
__device__ int    g_bidx[6 * B_];             // token id per bucket slot
__device__ float2 g_bg[6 * B_];               // (gate_lo, gate_hi) per bucket slot
__device__ float  g_vt[(size_t)B_ * D_];      // 256 MB tf32-rounded v
__device__ float  g_wp[(size_t)6 * NP * D_];  // 48 MB  pair-interleaved W^T

// ---------------- helpers ----------------
__device__ __forceinline__ uint32_t smem_u32(const void* p) {
    uint32_t a;
    asm("{ .reg .u64 t; cvta.to.shared.u64 t, %1; cvt.u32.u64 %0, t; }" : "=r"(a) : "l"(p));
    return a;
}
__device__ __forceinline__ float rna_tf32(float x) {
    float r; asm("cvt.rna.tf32.f32 %0, %1;" : "=f"(r) : "f"(x)); return r;
}
__device__ __forceinline__ void cp16(uint32_t s, const void* g) {
    asm volatile("cp.async.cg.shared.global [%0], [%1], 16;" :: "r"(s), "l"(g));
}
#define CP_COMMIT() asm volatile("cp.async.commit_group;" ::: "memory")
#define CP_WAIT(n)  asm volatile("cp.async.wait_group %0;" :: "n"(n) : "memory")

__device__ __forceinline__ void mma_tf32(float* d, const uint32_t* a, const uint32_t* b) {
    asm volatile(
        "mma.sync.aligned.m16n8k8.row.col.f32.tf32.tf32.f32 "
        "{%0,%1,%2,%3}, {%4,%5,%6,%7}, {%8,%9}, {%0,%1,%2,%3};"
        : "+f"(d[0]), "+f"(d[1]), "+f"(d[2]), "+f"(d[3])
        : "r"(a[0]), "r"(a[1]), "r"(a[2]), "r"(a[3]), "r"(b[0]), "r"(b[1]));
}

// ---------------------------------------------------------------------------
// Kernel 0: transpose + tf32-round expert_w into the 6 pair-interleaved copies
//           g_wp[pid][(o*2+which)][d]; also resets bucket counters.
// ---------------------------------------------------------------------------
__global__ __launch_bounds__(1024) void transpose_w_kernel(const float* __restrict__ ew) {
    if (blockIdx.x == 0 && blockIdx.y == 0 && blockIdx.z == 0 && threadIdx.x < 8 && threadIdx.y == 0)
        g_cnt[threadIdx.x] = 0;

    __shared__ float t[32][33];
    int e = blockIdx.z, o0 = blockIdx.y * 32, d0 = blockIdx.x * 32;
    int tx = threadIdx.x, ty = threadIdx.y;
    t[ty][tx] = rna_tf32(ew[((size_t)e * D_ + (d0 + ty)) * O_ + (o0 + tx)]);
    __syncthreads();

    // pair membership: expert e appears in 3 of the 6 pairs
    const int pp[4][3] = {{0,1,2},{0,3,4},{1,3,5},{2,4,5}};
    const int ww[4][3] = {{0,0,0},{1,0,0},{1,1,0},{1,1,1}};

    float val = t[tx][ty];
    int o = o0 + ty, d = d0 + tx;
    #pragma unroll
    for (int m = 0; m < 3; m++) {
        int pid = pp[e][m], which = ww[e][m];
        g_wp[((size_t)pid * NP + o * 2 + which) * D_ + d] = val;
    }
}

// ---------------------------------------------------------------------------
// Kernel 1: router (softmax + top-2) -> bucket scatter; fused tf32-round of v.
// ---------------------------------------------------------------------------
__global__ __launch_bounds__(256) void router_kernel(
    const float* __restrict__ v, const float* __restrict__ rw,
    float* __restrict__ routing_out, int write_routing)
{
    int warp = (blockIdx.x * blockDim.x + threadIdx.x) >> 5;
    int lane = threadIdx.x & 31;
    if (warp >= B_) return;

    const float4* v4  = (const float4*)(v + (size_t)warp * D_);
    float4*       vt4 = (float4*)(g_vt + (size_t)warp * D_);
    const float4* rw4 = (const float4*)rw;

    float4 acc = make_float4(0.f, 0.f, 0.f, 0.f);
    #pragma unroll 4
    for (int i = lane; i < D_ / 4; i += 32) {
        float4 vv = v4[i];
        float4 r0 = rw4[4 * i + 0];
        float4 r1 = rw4[4 * i + 1];
        float4 r2 = rw4[4 * i + 2];
        float4 r3 = rw4[4 * i + 3];
        acc.x += vv.x * r0.x + vv.y * r1.x + vv.z * r2.x + vv.w * r3.x;
        acc.y += vv.x * r0.y + vv.y * r1.y + vv.z * r2.y + vv.w * r3.y;
        acc.z += vv.x * r0.z + vv.y * r1.z + vv.z * r2.z + vv.w * r3.z;
        acc.w += vv.x * r0.w + vv.y * r1.w + vv.z * r2.w + vv.w * r3.w;
        vt4[i] = make_float4(rna_tf32(vv.x), rna_tf32(vv.y), rna_tf32(vv.z), rna_tf32(vv.w));
    }
    #pragma unroll
    for (int off = 16; off; off >>= 1) {
        acc.x += __shfl_xor_sync(0xFFFFFFFFu, acc.x, off);
        acc.y += __shfl_xor_sync(0xFFFFFFFFu, acc.y, off);
        acc.z += __shfl_xor_sync(0xFFFFFFFFu, acc.z, off);
        acc.w += __shfl_xor_sync(0xFFFFFFFFu, acc.w, off);
    }
    if (lane == 0) {
        float l[E_] = {acc.x, acc.y, acc.z, acc.w};
        float mx = fmaxf(fmaxf(l[0], l[1]), fmaxf(l[2], l[3]));
        float w[E_]; float s = 0.f;
        #pragma unroll
        for (int e = 0; e < E_; e++) { w[e] = __expf(l[e] - mx); s += w[e]; }
        float inv = 1.f / s;
        #pragma unroll
        for (int e = 0; e < E_; e++) w[e] *= inv;
        if (write_routing)
            *(float4*)&routing_out[(size_t)warp * E_] = make_float4(w[0], w[1], w[2], w[3]);

        int i1 = 0;
        #pragma unroll
        for (int e = 1; e < E_; e++) if (w[e] > w[i1]) i1 = e;
        int i2 = -1;
        #pragma unroll
        for (int e = 0; e < E_; e++) {
            if (e == i1) continue;
            if (i2 < 0 || w[e] > w[i2]) i2 = e;
        }
        float gs = 1.f / (w[i1] + w[i2]);
        int lo = min(i1, i2), hi = max(i1, i2);
        float g_lo = w[lo] * gs, g_hi = w[hi] * gs;
        int pid = (lo == 0) ? (hi - 1) : ((lo == 1) ? (hi + 1) : 5);

        int slot = atomicAdd(&g_cnt[pid], 1);
        g_bidx[pid * B_ + slot] = warp;
        g_bg[pid * B_ + slot] = make_float2(g_lo, g_hi);
    }
}

// ---------------------------------------------------------------------------
// Kernel 2: bucketed tf32 mma.sync GEMM, CTA tile 128x128 over N=512 per pair.
// A rows gathered via bucket index; epilogue combines the pair's two experts
// in-thread (cols o*2, o*2+1 land in acc[..][0..1]) and scatters to out[token].
// ---------------------------------------------------------------------------
__global__ __launch_bounds__(256, 2) void moe_mma_kernel(float* __restrict__ out)
{
    // --- map blockIdx.y -> (bucket pid, m-block) from runtime counts ---
    int my = blockIdx.y;
    int pid = -1, mb = 0;
    #pragma unroll
    for (int p = 0; p < 6; p++) {
        int nb = (g_cnt[p] + BM - 1) / BM;
        if (pid < 0) {
            if (my < nb) { pid = p; mb = my; }
            else my -= nb;
        }
    }
    if (pid < 0) return;
    const int cnt = g_cnt[pid];
    const int m0 = mb * BM;
    const int n0 = blockIdx.x * BN;

    extern __shared__ float sm[];
    __shared__ int s_idx[BM];
    uint32_t sb = smem_u32(sm);
    const uint32_t aOff[2] = {0u, 2u * STAGE_FLOATS * 4u};
    const uint32_t bOff[2] = {1u * STAGE_FLOATS * 4u, 3u * STAGE_FLOATS * 4u};

    const int tid = threadIdx.x;
    const int wid = tid >> 5, lane = tid & 31;
    const int warp_m = wid >> 2;
    const int warp_n = wid & 3;
    const int qid = lane >> 2;
    const int tig = lane & 3;

    if (tid < BM) {
        int s = m0 + tid;
        s_idx[tid] = g_bidx[pid * B_ + (s < cnt ? s : 0)];
    }
    __syncthreads();

    // per-thread gather pointers: rows r_i = (tid>>3) + i*32
    const int rbase = tid >> 3;
    const int kc = tid & 7;
    const float* aptr[4];
    #pragma unroll
    for (int i = 0; i < 4; i++)
        aptr[i] = g_vt + (size_t)s_idx[rbase + i * 32] * D_ + kc * 4;
    const float* Bsrc = g_wp + ((size_t)pid * NP + n0) * D_ + kc * 4;

    float acc[4][4][4] = {};

    // pipelined loads
    #pragma unroll
    for (int st = 0; st < 2; st++) {
        int k0 = st * BK;
        #pragma unroll
        for (int i = 0; i < 4; i++) {
            int r = rbase + i * 32;
            uint32_t dst = (uint32_t)(r * SA + kc * 4) * 4u;
            cp16(sb + aOff[st] + dst, aptr[i] + k0);
            cp16(sb + bOff[st] + dst, Bsrc + (size_t)r * D_ + k0);
        }
        CP_COMMIT();
    }

    for (int c = 0; c < NITER; c++) {
        int s = c & 1;
        if (c + 2 < NITER) { CP_WAIT(1); } else { CP_WAIT(0); }
        __syncthreads();

        const uint32_t* A  = (const uint32_t*)(sm) + (s ? 2 : 0) * STAGE_FLOATS;
        const uint32_t* Bv = (const uint32_t*)(sm) + (s ? 3 : 1) * STAGE_FLOATS;

        #pragma unroll
        for (int kk = 0; kk < 4; kk++) {
            uint32_t af[4][4], bf[4][2];
            int col = kk * 8 + tig;
            #pragma unroll
            for (int i = 0; i < 4; i++) {
                int r = warp_m * 64 + i * 16 + qid;
                af[i][0] = A[r * SA + col];
                af[i][1] = A[(r + 8) * SA + col];
                af[i][2] = A[r * SA + col + 4];
                af[i][3] = A[(r + 8) * SA + col + 4];
            }
            #pragma unroll
            for (int j = 0; j < 4; j++) {
                int n = warp_n * 32 + j * 8 + qid;
                bf[j][0] = Bv[n * SA + col];
                bf[j][1] = Bv[n * SA + col + 4];
            }
            #pragma unroll
            for (int i = 0; i < 4; i++)
                #pragma unroll
                for (int j = 0; j < 4; j++)
                    mma_tf32(acc[i][j], af[i], bf[j]);
        }
        __syncthreads();

        if (c + 2 < NITER) {
            int k0 = (c + 2) * BK;
            #pragma unroll
            for (int i = 0; i < 4; i++) {
                int r = rbase + i * 32;
                uint32_t dst = (uint32_t)(r * SA + kc * 4) * 4u;
                cp16(sb + aOff[s] + dst, aptr[i] + k0);
                cp16(sb + bOff[s] + dst, Bsrc + (size_t)r * D_ + k0);
            }
            CP_COMMIT();
        }
    }

    // ---- epilogue: combine pair gates, scatter to token rows ----
    #pragma unroll
    for (int i = 0; i < 4; i++) {
        int rA = warp_m * 64 + i * 16 + qid;   // local slot within m-block
        int sAg = m0 + rA, sBg = sAg + 8;
        bool vA = sAg < cnt, vB = sBg < cnt;
        int tokA = s_idx[rA], tokB = s_idx[rA + 8];
        float2 gA = vA ? g_bg[pid * B_ + sAg] : make_float2(0.f, 0.f);
        float2 gB = vB ? g_bg[pid * B_ + sBg] : make_float2(0.f, 0.f);
        #pragma unroll
        for (int j = 0; j < 4; j++) {
            int o = (n0 + warp_n * 32 + j * 8 + tig * 2) >> 1;
            if (vA) out[(size_t)tokA * O_ + o] = gA.x * acc[i][j][0] + gA.y * acc[i][j][1];
            if (vB) out[(size_t)tokB * O_ + o] = gB.x * acc[i][j][2] + gB.y * acc[i][j][3];
        }
    }
}

// ---------------------------------------------------------------------------
extern "C" void kernel_launch(void* const* d_in, const int* in_sizes, int n_in,
                              void* d_out, int out_size) {
    const float* v  = (const float*)d_in[0];   // [16384, 4096]
    const float* rw = (const float*)d_in[1];   // [4096, 4]
    const float* ew = (const float*)d_in[2];   // [4, 4096, 256]
    float* out = (float*)d_out;

    int write_routing = (out_size >= B_ * O_ + B_ * E_) ? 1 : 0;
    float* routing = write_routing ? (out + (size_t)B_ * O_) : nullptr;

    transpose_w_kernel<<<dim3(D_ / 32, O_ / 32, E_), dim3(32, 32)>>>(ew);
    router_kernel<<<B_ / 8, 256>>>(v, rw, routing, write_routing);

    const int smem_bytes = 4 * STAGE_FLOATS * sizeof(float);  // 72 KB
    cudaFuncSetAttribute(moe_mma_kernel, cudaFuncAttributeMaxDynamicSharedMemorySize, smem_bytes);
    moe_mma_kernel<<<dim3(NP / BN, MAXMB), 256, smem_bytes>>>(out);
}

// round 5
// speedup vs baseline: 4.8244x; 1.0789x over previous
#include <cuda_runtime.h>
#include <cstdint>
#include <cstddef>

#define B_ 16384
#define D_ 4096
#define E_ 4
#define O_ 256
#define NP 512           // pair-bucket GEMM width: 2 experts * 256, n = o*2 + which

#define BM 128
#define BN 256
#define BK 32
#define SA 36            // padded smem row stride (floats) -> conflict-free frags
#define NITER (D_/BK)    // 128
#define A_FLOATS (BM * SA)            // 4608
#define B_FLOATS (BN * SA)            // 9216
#define STAGE_FLOATS (A_FLOATS + B_FLOATS)  // 13824
#define NSTAGE 3
#define MAXMB (B_/BM + 5)   // 133: worst-case total m-blocks over 6 buckets

// scratch
__device__ int    g_cnt[8];                   // bucket counts (reset each launch)
__device__ int    g_bidx[6 * B_];             // token id per bucket slot
__device__ float2 g_bg[6 * B_];               // (gate_lo, gate_hi) per bucket slot
__device__ float  g_wp[(size_t)6 * NP * D_];  // 48 MB pair-interleaved tf32 W^T

// ---------------- helpers ----------------
__device__ __forceinline__ uint32_t smem_u32(const void* p) {
    uint32_t a;
    asm("{ .reg .u64 t; cvta.to.shared.u64 t, %1; cvt.u32.u64 %0, t; }" : "=r"(a) : "l"(p));
    return a;
}
__device__ __forceinline__ float rna_tf32(float x) {
    float r; asm("cvt.rna.tf32.f32 %0, %1;" : "=f"(r) : "f"(x)); return r;
}
__device__ __forceinline__ uint32_t bits_tf32(uint32_t x) {
    uint32_t r;
    asm("cvt.rna.tf32.f32 %0, %1;" : "=r"(r) : "f"(__uint_as_float(x)));
    return r;
}
__device__ __forceinline__ void cp16(uint32_t s, const void* g) {
    asm volatile("cp.async.cg.shared.global [%0], [%1], 16;" :: "r"(s), "l"(g));
}
#define CP_COMMIT() asm volatile("cp.async.commit_group;" ::: "memory")
#define CP_WAIT(n)  asm volatile("cp.async.wait_group %0;" :: "n"(n) : "memory")

__device__ __forceinline__ void mma_tf32(float* d, const uint32_t* a, const uint32_t* b) {
    asm volatile(
        "mma.sync.aligned.m16n8k8.row.col.f32.tf32.tf32.f32 "
        "{%0,%1,%2,%3}, {%4,%5,%6,%7}, {%8,%9}, {%0,%1,%2,%3};"
        : "+f"(d[0]), "+f"(d[1]), "+f"(d[2]), "+f"(d[3])
        : "r"(a[0]), "r"(a[1]), "r"(a[2]), "r"(a[3]), "r"(b[0]), "r"(b[1]));
}

// ---------------------------------------------------------------------------
// Kernel 0: transpose + tf32-round expert_w into 6 pair-interleaved copies
//           g_wp[pid][(o*2+which)][d], float4 coalesced stores. Resets g_cnt.
// ---------------------------------------------------------------------------
__global__ __launch_bounds__(256) void transpose_w_kernel(const float* __restrict__ ew) {
    if (blockIdx.x == 0 && blockIdx.y == 0 && blockIdx.z == 0 && threadIdx.x < 8)
        g_cnt[threadIdx.x] = 0;

    __shared__ float t[32][33];   // t[d_local][o_local]
    const int e = blockIdx.z, o0 = blockIdx.y * 32, d0 = blockIdx.x * 32;
    const int tx = threadIdx.x & 31;
    const int ty = threadIdx.x >> 5;   // 0..7

    #pragma unroll
    for (int k = 0; k < 4; k++) {
        int dl = ty + 8 * k;
        t[dl][tx] = rna_tf32(ew[((size_t)e * D_ + (d0 + dl)) * O_ + (o0 + tx)]);
    }
    __syncthreads();

    // pair membership: expert e appears in 3 of the 6 pairs
    const int pp[4][3] = {{0,1,2},{0,3,4},{1,3,5},{2,4,5}};
    const int ww[4][3] = {{0,0,0},{1,0,0},{1,1,0},{1,1,1}};

    const int ol = threadIdx.x >> 3;   // 0..31
    const int q  = threadIdx.x & 7;    // d quad 0..7
    float4 val = make_float4(t[q*4+0][ol], t[q*4+1][ol], t[q*4+2][ol], t[q*4+3][ol]);
    const int o = o0 + ol, d = d0 + q * 4;
    #pragma unroll
    for (int m = 0; m < 3; m++) {
        int pid = pp[e][m], which = ww[e][m];
        *(float4*)&g_wp[((size_t)pid * NP + o * 2 + which) * D_ + d] = val;
    }
}

// ---------------------------------------------------------------------------
// Kernel 1: router (softmax + top-2) -> bucket scatter. Read-only on v.
// ---------------------------------------------------------------------------
__global__ __launch_bounds__(256) void router_kernel(
    const float* __restrict__ v, const float* __restrict__ rw,
    float* __restrict__ routing_out, int write_routing)
{
    int warp = (blockIdx.x * blockDim.x + threadIdx.x) >> 5;
    int lane = threadIdx.x & 31;
    if (warp >= B_) return;

    const float4* v4  = (const float4*)(v + (size_t)warp * D_);
    const float4* rw4 = (const float4*)rw;

    float4 acc = make_float4(0.f, 0.f, 0.f, 0.f);
    #pragma unroll 4
    for (int i = lane; i < D_ / 4; i += 32) {
        float4 vv = v4[i];
        float4 r0 = rw4[4 * i + 0];
        float4 r1 = rw4[4 * i + 1];
        float4 r2 = rw4[4 * i + 2];
        float4 r3 = rw4[4 * i + 3];
        acc.x += vv.x * r0.x + vv.y * r1.x + vv.z * r2.x + vv.w * r3.x;
        acc.y += vv.x * r0.y + vv.y * r1.y + vv.z * r2.y + vv.w * r3.y;
        acc.z += vv.x * r0.z + vv.y * r1.z + vv.z * r2.z + vv.w * r3.z;
        acc.w += vv.x * r0.w + vv.y * r1.w + vv.z * r2.w + vv.w * r3.w;
    }
    #pragma unroll
    for (int off = 16; off; off >>= 1) {
        acc.x += __shfl_xor_sync(0xFFFFFFFFu, acc.x, off);
        acc.y += __shfl_xor_sync(0xFFFFFFFFu, acc.y, off);
        acc.z += __shfl_xor_sync(0xFFFFFFFFu, acc.z, off);
        acc.w += __shfl_xor_sync(0xFFFFFFFFu, acc.w, off);
    }
    if (lane == 0) {
        float l[E_] = {acc.x, acc.y, acc.z, acc.w};
        float mx = fmaxf(fmaxf(l[0], l[1]), fmaxf(l[2], l[3]));
        float w[E_]; float s = 0.f;
        #pragma unroll
        for (int e = 0; e < E_; e++) { w[e] = __expf(l[e] - mx); s += w[e]; }
        float inv = 1.f / s;
        #pragma unroll
        for (int e = 0; e < E_; e++) w[e] *= inv;
        if (write_routing)
            *(float4*)&routing_out[(size_t)warp * E_] = make_float4(w[0], w[1], w[2], w[3]);

        int i1 = 0;
        #pragma unroll
        for (int e = 1; e < E_; e++) if (w[e] > w[i1]) i1 = e;
        int i2 = -1;
        #pragma unroll
        for (int e = 0; e < E_; e++) {
            if (e == i1) continue;
            if (i2 < 0 || w[e] > w[i2]) i2 = e;
        }
        float gs = 1.f / (w[i1] + w[i2]);
        int lo = min(i1, i2), hi = max(i1, i2);
        float g_lo = w[lo] * gs, g_hi = w[hi] * gs;
        int pid = (lo == 0) ? (hi - 1) : ((lo == 1) ? (hi + 1) : 5);

        int slot = atomicAdd(&g_cnt[pid], 1);
        g_bidx[pid * B_ + slot] = warp;
        g_bg[pid * B_ + slot] = make_float2(g_lo, g_hi);
    }
}

// ---------------------------------------------------------------------------
// Kernel 2: bucketed tf32 mma.sync GEMM. CTA tile 128x256, warp tile 64x64,
// 3-stage cp.async. A gathered from raw v; tf32 rounding applied in-register
// to A fragments. Epilogue: in-thread pair-gate combine, scatter to tokens.
// ---------------------------------------------------------------------------
__global__ __launch_bounds__(256, 1) void moe_mma_kernel(
    const float* __restrict__ v, float* __restrict__ out)
{
    // --- map blockIdx.y -> (bucket pid, m-block) from runtime counts ---
    int my = blockIdx.y;
    int pid = -1, mb = 0;
    #pragma unroll
    for (int p = 0; p < 6; p++) {
        int nb = (g_cnt[p] + BM - 1) / BM;
        if (pid < 0) {
            if (my < nb) { pid = p; mb = my; }
            else my -= nb;
        }
    }
    if (pid < 0) return;
    const int cnt = g_cnt[pid];
    const int m0 = mb * BM;
    const int n0 = blockIdx.x * BN;

    extern __shared__ float sm[];
    __shared__ int s_idx[BM];
    uint32_t sb = smem_u32(sm);

    const int tid = threadIdx.x;
    const int wid = tid >> 5, lane = tid & 31;
    const int warp_m = wid >> 2;        // 0..1 (64 rows)
    const int warp_n = wid & 3;         // 0..3 (64 cols)
    const int qid = lane >> 2;          // 0..7
    const int tig = lane & 3;           // 0..3

    if (tid < BM) {
        int s = m0 + tid;
        s_idx[tid] = g_bidx[pid * B_ + (s < cnt ? s : 0)];
    }
    __syncthreads();

    // gather pointers: A rows r_i = (tid>>3) + i*32 (i<4); B rows + i*32 (i<8)
    const int rbase = tid >> 3;
    const int kc = tid & 7;
    const float* aptr[4];
    #pragma unroll
    for (int i = 0; i < 4; i++)
        aptr[i] = v + (size_t)s_idx[rbase + i * 32] * D_ + kc * 4;
    const float* Bsrc = g_wp + ((size_t)pid * NP + n0) * D_ + kc * 4;

    float acc[4][8][4] = {};

    // prologue: stages 0..2 <- chunks 0..2
    #pragma unroll
    for (int st = 0; st < NSTAGE; st++) {
        int k0 = st * BK;
        uint32_t ab = sb + (uint32_t)st * STAGE_FLOATS * 4u;
        uint32_t bb = ab + (uint32_t)A_FLOATS * 4u;
        #pragma unroll
        for (int i = 0; i < 4; i++) {
            uint32_t dst = (uint32_t)((rbase + i * 32) * SA + kc * 4) * 4u;
            cp16(ab + dst, aptr[i] + k0);
        }
        #pragma unroll
        for (int i = 0; i < 8; i++) {
            int r = rbase + i * 32;
            uint32_t dst = (uint32_t)(r * SA + kc * 4) * 4u;
            cp16(bb + dst, Bsrc + (size_t)r * D_ + k0);
        }
        CP_COMMIT();
    }

    int s = 0;
    #pragma unroll 1
    for (int c = 0; c < NITER; c++) {
        if (c + 3 <= NITER)      { CP_WAIT(2); }
        else if (c + 2 == NITER) { CP_WAIT(1); }
        else                     { CP_WAIT(0); }
        __syncthreads();

        const uint32_t* A  = (const uint32_t*)(sm) + s * STAGE_FLOATS;
        const uint32_t* Bv = A + A_FLOATS;

        #pragma unroll
        for (int kk = 0; kk < 4; kk++) {
            uint32_t af[4][4], bf[8][2];
            int col = kk * 8 + tig;
            #pragma unroll
            for (int i = 0; i < 4; i++) {
                int r = warp_m * 64 + i * 16 + qid;
                af[i][0] = bits_tf32(A[r * SA + col]);
                af[i][1] = bits_tf32(A[(r + 8) * SA + col]);
                af[i][2] = bits_tf32(A[r * SA + col + 4]);
                af[i][3] = bits_tf32(A[(r + 8) * SA + col + 4]);
            }
            #pragma unroll
            for (int j = 0; j < 8; j++) {
                int n = warp_n * 64 + j * 8 + qid;
                bf[j][0] = Bv[n * SA + col];
                bf[j][1] = Bv[n * SA + col + 4];
            }
            #pragma unroll
            for (int i = 0; i < 4; i++)
                #pragma unroll
                for (int j = 0; j < 8; j++)
                    mma_tf32(acc[i][j], af[i], bf[j]);
        }
        __syncthreads();

        if (c + 3 < NITER) {
            int k0 = (c + 3) * BK;
            uint32_t ab = sb + (uint32_t)s * STAGE_FLOATS * 4u;
            uint32_t bb = ab + (uint32_t)A_FLOATS * 4u;
            #pragma unroll
            for (int i = 0; i < 4; i++) {
                uint32_t dst = (uint32_t)((rbase + i * 32) * SA + kc * 4) * 4u;
                cp16(ab + dst, aptr[i] + k0);
            }
            #pragma unroll
            for (int i = 0; i < 8; i++) {
                int r = rbase + i * 32;
                uint32_t dst = (uint32_t)(r * SA + kc * 4) * 4u;
                cp16(bb + dst, Bsrc + (size_t)r * D_ + k0);
            }
            CP_COMMIT();
        }
        s = (s + 1 == NSTAGE) ? 0 : s + 1;
    }

    // ---- epilogue: combine pair gates, scatter to token rows ----
    #pragma unroll
    for (int i = 0; i < 4; i++) {
        int rA = warp_m * 64 + i * 16 + qid;
        int sAg = m0 + rA, sBg = sAg + 8;
        bool vA = sAg < cnt, vB = sBg < cnt;
        int tokA = s_idx[rA], tokB = s_idx[rA + 8];
        float2 gA = vA ? g_bg[pid * B_ + sAg] : make_float2(0.f, 0.f);
        float2 gB = vB ? g_bg[pid * B_ + sBg] : make_float2(0.f, 0.f);
        #pragma unroll
        for (int j = 0; j < 8; j++) {
            int o = (n0 + warp_n * 64 + j * 8 + tig * 2) >> 1;
            if (vA) out[(size_t)tokA * O_ + o] = gA.x * acc[i][j][0] + gA.y * acc[i][j][1];
            if (vB) out[(size_t)tokB * O_ + o] = gB.x * acc[i][j][2] + gB.y * acc[i][j][3];
        }
    }
}

// ---------------------------------------------------------------------------
extern "C" void kernel_launch(void* const* d_in, const int* in_sizes, int n_in,
                              void* d_out, int out_size) {
    const float* v  = (const float*)d_in[0];   // [16384, 4096]
    const float* rw = (const float*)d_in[1];   // [4096, 4]
    const float* ew = (const float*)d_in[2];   // [4, 4096, 256]
    float* out = (float*)d_out;

    int write_routing = (out_size >= B_ * O_ + B_ * E_) ? 1 : 0;
    float* routing = write_routing ? (out + (size_t)B_ * O_) : nullptr;

    transpose_w_kernel<<<dim3(D_ / 32, O_ / 32, E_), 256>>>(ew);
    router_kernel<<<B_ / 8, 256>>>(v, rw, routing, write_routing);

    const int smem_bytes = NSTAGE * STAGE_FLOATS * sizeof(float);  // 162 KB
    cudaFuncSetAttribute(moe_mma_kernel, cudaFuncAttributeMaxDynamicSharedMemorySize, smem_bytes);
    moe_mma_kernel<<<dim3(NP / BN, MAXMB), 256, smem_bytes>>>(v, out);
}

// round 7
// speedup vs baseline: 6.7224x; 1.3934x over previous
#include <cuda_runtime.h>
#include <cuda_fp16.h>
#include <cstdint>
#include <cstddef>

#define B_ 16384
#define D_ 4096
#define E_ 4
#define O_ 256
#define NP 512           // pair-bucket GEMM width: 2 experts * 256, n = o*2 + which

#define BM 128
#define BN 256
#define BK 32
#define SAH 40           // smem row stride in halves (80B): conflict-free LDSM partition
#define NITER (D_/BK)    // 128
#define A_BYTES (BM * SAH * 2)        // 10240
#define B_BYTES (BN * SAH * 2)        // 20480
#define STAGE_BYTES (A_BYTES + B_BYTES)  // 30720
#define NSTAGE 4
#define MAXMB (B_/BM + 5)   // 133: worst-case total m-blocks over 6 buckets

// scratch
__device__ int    g_cnt[8];                     // bucket counts (reset each launch)
__device__ int    g_bidx[6 * B_];               // token id per bucket slot
__device__ float2 g_bg[6 * B_];                 // (gate_lo, gate_hi) per bucket slot
__device__ __half g_vh[(size_t)B_ * D_];        // 128 MB fp16 v
__device__ __half g_wp[(size_t)6 * NP * D_];    // 24 MB  pair-interleaved fp16 W^T

// ---------------- helpers ----------------
__device__ __forceinline__ uint32_t smem_u32(const void* p) {
    uint32_t a;
    asm("{ .reg .u64 t; cvta.to.shared.u64 t, %1; cvt.u32.u64 %0, t; }" : "=r"(a) : "l"(p));
    return a;
}
__device__ __forceinline__ uint32_t h2_bits(__half2 h) {
    uint32_t u;
    asm("mov.b32 %0, %1;" : "=r"(u) : "r"(*(uint32_t*)&h));
    return u;
}
__device__ __forceinline__ void cp16(uint32_t s, const void* g) {
    asm volatile("cp.async.cg.shared.global [%0], [%1], 16;" :: "r"(s), "l"(g));
}
#define CP_COMMIT() asm volatile("cp.async.commit_group;" ::: "memory")
#define CP_WAIT(n)  asm volatile("cp.async.wait_group %0;" :: "n"(n) : "memory")

#define LDSM4(r0, r1, r2, r3, addr) \
    asm volatile("ldmatrix.sync.aligned.m8n8.x4.shared.b16 {%0,%1,%2,%3}, [%4];" \
                 : "=r"(r0), "=r"(r1), "=r"(r2), "=r"(r3) : "r"(addr))

__device__ __forceinline__ void mma_f16(float* d, const uint32_t* a, const uint32_t* b) {
    asm volatile(
        "mma.sync.aligned.m16n8k16.row.col.f32.f16.f16.f32 "
        "{%0,%1,%2,%3}, {%4,%5,%6,%7}, {%8,%9}, {%0,%1,%2,%3};"
        : "+f"(d[0]), "+f"(d[1]), "+f"(d[2]), "+f"(d[3])
        : "r"(a[0]), "r"(a[1]), "r"(a[2]), "r"(a[3]), "r"(b[0]), "r"(b[1]));
}

// ---------------------------------------------------------------------------
// Kernel 0: transpose + fp16-round expert_w into 6 pair-interleaved copies
//           g_wp[pid][(o*2+which)][d]. Resets bucket counters.
// ---------------------------------------------------------------------------
__global__ __launch_bounds__(256) void transpose_w_kernel(const float* __restrict__ ew) {
    if (blockIdx.x == 0 && blockIdx.y == 0 && blockIdx.z == 0 && threadIdx.x < 8)
        g_cnt[threadIdx.x] = 0;

    __shared__ float t[32][33];   // t[d_local][o_local]
    const int e = blockIdx.z, o0 = blockIdx.y * 32, d0 = blockIdx.x * 32;
    const int tx = threadIdx.x & 31;
    const int ty = threadIdx.x >> 5;   // 0..7

    #pragma unroll
    for (int k = 0; k < 4; k++) {
        int dl = ty + 8 * k;
        t[dl][tx] = ew[((size_t)e * D_ + (d0 + dl)) * O_ + (o0 + tx)];
    }
    __syncthreads();

    const int pp[4][3] = {{0,1,2},{0,3,4},{1,3,5},{2,4,5}};
    const int ww[4][3] = {{0,0,0},{1,0,0},{1,1,0},{1,1,1}};

    const int ol = threadIdx.x >> 3;   // 0..31
    const int q  = threadIdx.x & 7;    // d quad 0..7
    __half2 h01 = __floats2half2_rn(t[q*4+0][ol], t[q*4+1][ol]);
    __half2 h23 = __floats2half2_rn(t[q*4+2][ol], t[q*4+3][ol]);
    uint2 val = make_uint2(h2_bits(h01), h2_bits(h23));
    const int o = o0 + ol, d = d0 + q * 4;
    #pragma unroll
    for (int m = 0; m < 3; m++) {
        int pid = pp[e][m], which = ww[e][m];
        *(uint2*)&g_wp[((size_t)pid * NP + o * 2 + which) * D_ + d] = val;
    }
}

// ---------------------------------------------------------------------------
// Kernel 1: router (softmax + top-2) -> bucket scatter; fused fp16 cast of v.
// ---------------------------------------------------------------------------
__global__ __launch_bounds__(256) void router_kernel(
    const float* __restrict__ v, const float* __restrict__ rw,
    float* __restrict__ routing_out, int write_routing)
{
    int warp = (blockIdx.x * blockDim.x + threadIdx.x) >> 5;
    int lane = threadIdx.x & 31;
    if (warp >= B_) return;

    const float4* v4 = (const float4*)(v + (size_t)warp * D_);
    uint2*       vh2 = (uint2*)(g_vh + (size_t)warp * D_);
    const float4* rw4 = (const float4*)rw;

    float4 acc = make_float4(0.f, 0.f, 0.f, 0.f);
    #pragma unroll 4
    for (int i = lane; i < D_ / 4; i += 32) {
        float4 vv = v4[i];
        float4 r0 = rw4[4 * i + 0];
        float4 r1 = rw4[4 * i + 1];
        float4 r2 = rw4[4 * i + 2];
        float4 r3 = rw4[4 * i + 3];
        acc.x += vv.x * r0.x + vv.y * r1.x + vv.z * r2.x + vv.w * r3.x;
        acc.y += vv.x * r0.y + vv.y * r1.y + vv.z * r2.y + vv.w * r3.y;
        acc.z += vv.x * r0.z + vv.y * r1.z + vv.z * r2.z + vv.w * r3.z;
        acc.w += vv.x * r0.w + vv.y * r1.w + vv.z * r2.w + vv.w * r3.w;
        __half2 h01 = __floats2half2_rn(vv.x, vv.y);
        __half2 h23 = __floats2half2_rn(vv.z, vv.w);
        vh2[i] = make_uint2(h2_bits(h01), h2_bits(h23));
    }
    #pragma unroll
    for (int off = 16; off; off >>= 1) {
        acc.x += __shfl_xor_sync(0xFFFFFFFFu, acc.x, off);
        acc.y += __shfl_xor_sync(0xFFFFFFFFu, acc.y, off);
        acc.z += __shfl_xor_sync(0xFFFFFFFFu, acc.z, off);
        acc.w += __shfl_xor_sync(0xFFFFFFFFu, acc.w, off);
    }
    if (lane == 0) {
        float l[E_] = {acc.x, acc.y, acc.z, acc.w};
        float mx = fmaxf(fmaxf(l[0], l[1]), fmaxf(l[2], l[3]));
        float w[E_]; float s = 0.f;
        #pragma unroll
        for (int e = 0; e < E_; e++) { w[e] = __expf(l[e] - mx); s += w[e]; }
        float inv = 1.f / s;
        #pragma unroll
        for (int e = 0; e < E_; e++) w[e] *= inv;
        if (write_routing)
            *(float4*)&routing_out[(size_t)warp * E_] = make_float4(w[0], w[1], w[2], w[3]);

        int i1 = 0;
        #pragma unroll
        for (int e = 1; e < E_; e++) if (w[e] > w[i1]) i1 = e;
        int i2 = -1;
        #pragma unroll
        for (int e = 0; e < E_; e++) {
            if (e == i1) continue;
            if (i2 < 0 || w[e] > w[i2]) i2 = e;
        }
        float gs = 1.f / (w[i1] + w[i2]);
        int lo = min(i1, i2), hi = max(i1, i2);
        float g_lo = w[lo] * gs, g_hi = w[hi] * gs;
        int pid = (lo == 0) ? (hi - 1) : ((lo == 1) ? (hi + 1) : 5);

        int slot = atomicAdd(&g_cnt[pid], 1);
        g_bidx[pid * B_ + slot] = warp;
        g_bg[pid * B_ + slot] = make_float2(g_lo, g_hi);
    }
}

// ---------------------------------------------------------------------------
// Kernel 2: bucketed fp16 mma.sync GEMM (m16n8k16). CTA tile 128x256, warp
// tile 64x64, 4-stage cp.async, ldmatrix.x4 fragment loads. Epilogue combines
// the pair's two experts in-thread and scatters to token rows.
// ---------------------------------------------------------------------------
__global__ __launch_bounds__(256, 1) void moe_mma_kernel(float* __restrict__ out)
{
    // --- map blockIdx.y -> (bucket pid, m-block) from runtime counts ---
    int my = blockIdx.y;
    int pid = -1, mb = 0;
    #pragma unroll
    for (int p = 0; p < 6; p++) {
        int nb = (g_cnt[p] + BM - 1) / BM;
        if (pid < 0) {
            if (my < nb) { pid = p; mb = my; }
            else my -= nb;
        }
    }
    if (pid < 0) return;
    const int cnt = g_cnt[pid];
    const int m0 = mb * BM;
    const int n0 = blockIdx.x * BN;

    extern __shared__ char smraw[];
    __shared__ int s_idx[BM];
    uint32_t sb = smem_u32(smraw);

    const int tid = threadIdx.x;
    const int wid = tid >> 5, lane = tid & 31;
    const int warp_m = wid >> 2;        // 0..1 (64 rows)
    const int warp_n = wid & 3;         // 0..3 (64 cols)
    const int qid = lane >> 2;          // 0..7
    const int tig = lane & 3;           // 0..3

    if (tid < BM) {
        int s = m0 + tid;
        s_idx[tid] = g_bidx[pid * B_ + (s < cnt ? s : 0)];
    }
    __syncthreads();

    // loaders: 16B = 8 halves per cp16. A: rows (tid>>2)+{0,64}; B: +{0,64,128,192}
    const int lrow = tid >> 2;          // 0..63
    const int kc = tid & 3;             // 16B chunk within 32-half row
    const __half* aptr[2];
    #pragma unroll
    for (int i = 0; i < 2; i++)
        aptr[i] = g_vh + (size_t)s_idx[lrow + i * 64] * D_ + kc * 8;
    const __half* Bsrc = g_wp + ((size_t)pid * NP + n0) * D_ + kc * 8;

    float acc[4][8][4] = {};

    // prologue: stages 0..NSTAGE-1 <- chunks 0..NSTAGE-1
    #pragma unroll
    for (int st = 0; st < NSTAGE; st++) {
        int k0 = st * BK;
        uint32_t ab = sb + (uint32_t)st * STAGE_BYTES;
        uint32_t bb = ab + (uint32_t)A_BYTES;
        #pragma unroll
        for (int i = 0; i < 2; i++)
            cp16(ab + (uint32_t)((lrow + i * 64) * SAH + kc * 8) * 2u, aptr[i] + k0);
        #pragma unroll
        for (int i = 0; i < 4; i++) {
            int r = lrow + i * 64;
            cp16(bb + (uint32_t)(r * SAH + kc * 8) * 2u, Bsrc + (size_t)r * D_ + k0);
        }
        CP_COMMIT();
    }

    // per-thread ldmatrix lane addressing
    const int frow = (lane & 7) + 8 * ((lane >> 3) & 1);  // row within 16-row frag
    const int foct = lane >> 4;                           // k-octet select (0/1)
    const uint32_t aoffb = (uint32_t)((warp_m * 64 + frow) * SAH * 2 + foct * 16);
    const uint32_t boffb = (uint32_t)((warp_n * 64 + frow) * SAH * 2 + foct * 16);

    int s = 0;
    #pragma unroll 1
    for (int c = 0; c < NITER; c++) {
        if (c + NSTAGE <= NITER)      { CP_WAIT(NSTAGE - 1); }
        else if (c + 3 == NITER)      { CP_WAIT(2); }
        else if (c + 2 == NITER)      { CP_WAIT(1); }
        else                          { CP_WAIT(0); }
        __syncthreads();

        uint32_t abase = sb + (uint32_t)s * STAGE_BYTES + aoffb;
        uint32_t bbase = sb + (uint32_t)s * STAGE_BYTES + (uint32_t)A_BYTES + boffb;

        #pragma unroll
        for (int kk = 0; kk < 2; kk++) {
            uint32_t af[4][4], bf[8][2];
            #pragma unroll
            for (int i = 0; i < 4; i++)
                LDSM4(af[i][0], af[i][1], af[i][2], af[i][3],
                      abase + (uint32_t)(i * 16 * SAH * 2) + (uint32_t)(kk * 32));
            #pragma unroll
            for (int jp = 0; jp < 4; jp++)
                LDSM4(bf[2*jp][0], bf[2*jp+1][0], bf[2*jp][1], bf[2*jp+1][1],
                      bbase + (uint32_t)(jp * 16 * SAH * 2) + (uint32_t)(kk * 32));
            #pragma unroll
            for (int i = 0; i < 4; i++)
                #pragma unroll
                for (int j = 0; j < 8; j++)
                    mma_f16(acc[i][j], af[i], bf[j]);
        }
        __syncthreads();

        if (c + NSTAGE < NITER) {
            int k0 = (c + NSTAGE) * BK;
            uint32_t ab = sb + (uint32_t)s * STAGE_BYTES;
            uint32_t bb = ab + (uint32_t)A_BYTES;
            #pragma unroll
            for (int i = 0; i < 2; i++)
                cp16(ab + (uint32_t)((lrow + i * 64) * SAH + kc * 8) * 2u, aptr[i] + k0);
            #pragma unroll
            for (int i = 0; i < 4; i++) {
                int r = lrow + i * 64;
                cp16(bb + (uint32_t)(r * SAH + kc * 8) * 2u, Bsrc + (size_t)r * D_ + k0);
            }
            CP_COMMIT();
        }
        s = (s + 1 == NSTAGE) ? 0 : s + 1;
    }

    // ---- epilogue: combine pair gates, scatter to token rows ----
    #pragma unroll
    for (int i = 0; i < 4; i++) {
        int rA = warp_m * 64 + i * 16 + qid;
        int sAg = m0 + rA, sBg = sAg + 8;
        bool vA = sAg < cnt, vB = sBg < cnt;
        int tokA = s_idx[rA], tokB = s_idx[rA + 8];
        float2 gA = vA ? g_bg[pid * B_ + sAg] : make_float2(0.f, 0.f);
        float2 gB = vB ? g_bg[pid * B_ + sBg] : make_float2(0.f, 0.f);
        #pragma unroll
        for (int j = 0; j < 8; j++) {
            int o = (n0 + warp_n * 64 + j * 8 + tig * 2) >> 1;
            if (vA) out[(size_t)tokA * O_ + o] = gA.x * acc[i][j][0] + gA.y * acc[i][j][1];
            if (vB) out[(size_t)tokB * O_ + o] = gB.x * acc[i][j][2] + gB.y * acc[i][j][3];
        }
    }
}

// ---------------------------------------------------------------------------
extern "C" void kernel_launch(void* const* d_in, const int* in_sizes, int n_in,
                              void* d_out, int out_size) {
    const float* v  = (const float*)d_in[0];   // [16384, 4096]
    const float* rw = (const float*)d_in[1];   // [4096, 4]
    const float* ew = (const float*)d_in[2];   // [4, 4096, 256]
    float* out = (float*)d_out;

    int write_routing = (out_size >= B_ * O_ + B_ * E_) ? 1 : 0;
    float* routing = write_routing ? (out + (size_t)B_ * O_) : nullptr;

    transpose_w_kernel<<<dim3(D_ / 32, O_ / 32, E_), 256>>>(ew);
    router_kernel<<<B_ / 8, 256>>>(v, rw, routing, write_routing);

    const int smem_bytes = NSTAGE * STAGE_BYTES;  // 120 KB
    cudaFuncSetAttribute(moe_mma_kernel, cudaFuncAttributeMaxDynamicSharedMemorySize, smem_bytes);
    moe_mma_kernel<<<dim3(NP / BN, MAXMB), 256, smem_bytes>>>(out);
}